// round 10
// baseline (speedup 1.0000x reference)
#include <cuda_runtime.h>
#include <cstdint>

// out[b,c,h,w] = x[b,c,2h,2w] * 0.5f     (Haar DWT subband sum collapses to this)
// x:  [16, 64, 512, 512] fp32,  out: [16, 64, 256, 256] fp32
//
// Identical to the R8 kernel (flat grid, MLP=4, warp-coalesced, single index
// decomposition) with ONE change: stores use the default write-back policy
// instead of .cs, so L2 can batch the write stream into larger DRAM bursts
// (isolated test of store policy; R7 confounded it with the persistent loop).
//
//   pair = p & 127, orow = (p>>7) & 255, bc = p >> 15
//   input float4 index = bc*65536 + orow*256 + pair   (even input row 2*orow)
//   block owns 1024 aligned pairs -> in_idx_k = in_idx_0 + 512k

__global__ __launch_bounds__(256) void haar_sum_kernel(
    const float4* __restrict__ x, float2* __restrict__ out)
{
    const unsigned i0 = blockIdx.x * 1024u + threadIdx.x;

    // single index decomposition
    const unsigned pair = i0 & 127u;
    const unsigned orow = (i0 >> 7) & 255u;
    const unsigned bc   = i0 >> 15;
    const long long a0  = ((long long)bc << 16) + ((long long)orow << 8) + pair;

    // four independent streaming loads (rows r, r+2, r+4, r+6)
    float4 v0 = __ldcs(&x[a0]);
    float4 v1 = __ldcs(&x[a0 +  512]);
    float4 v2 = __ldcs(&x[a0 + 1024]);
    float4 v3 = __ldcs(&x[a0 + 1536]);

    float2 o0, o1, o2, o3;
    o0.x = v0.x * 0.5f;  o0.y = v0.z * 0.5f;
    o1.x = v1.x * 0.5f;  o1.y = v1.z * 0.5f;
    o2.x = v2.x * 0.5f;  o2.y = v2.z * 0.5f;
    o3.x = v3.x * 0.5f;  o3.y = v3.z * 0.5f;

    // default write-back stores: L2 batches the write stream to DRAM
    out[i0]        = o0;
    out[i0 + 256u] = o1;
    out[i0 + 512u] = o2;
    out[i0 + 768u] = o3;
}

extern "C" void kernel_launch(void* const* d_in, const int* in_sizes, int n_in,
                              void* d_out, int out_size)
{
    const float4* x = (const float4*)d_in[0];
    float2* out     = (float2*)d_out;

    // out_size = 67,108,864 floats -> 33,554,432 pairs -> 1024 pairs per block
    long long n_pairs = (long long)out_size / 2;
    long long blocks  = n_pairs / 1024;                // 32768

    haar_sum_kernel<<<(unsigned)blocks, 256>>>(x, out);
}

// round 11
// speedup vs baseline: 1.0003x; 1.0003x over previous
#include <cuda_runtime.h>
#include <cstdint>

// out[b,c,h,w] = x[b,c,2h,2w] * 0.5f     (Haar DWT subband sum collapses to this)
// x:  [16, 64, 512, 512] fp32,  out: [16, 64, 256, 256] fp32
//
// Identical to the R8 kernel (flat grid, MLP=4, warp-coalesced, single index
// decomposition) with ONE change: stores use the default write-back policy
// instead of .cs, so L2 can batch the write stream into larger DRAM bursts
// (isolated test of store policy; R7 confounded it with the persistent loop).
//
//   pair = p & 127, orow = (p>>7) & 255, bc = p >> 15
//   input float4 index = bc*65536 + orow*256 + pair   (even input row 2*orow)
//   block owns 1024 aligned pairs -> in_idx_k = in_idx_0 + 512k

__global__ __launch_bounds__(256) void haar_sum_kernel(
    const float4* __restrict__ x, float2* __restrict__ out)
{
    const unsigned i0 = blockIdx.x * 1024u + threadIdx.x;

    // single index decomposition
    const unsigned pair = i0 & 127u;
    const unsigned orow = (i0 >> 7) & 255u;
    const unsigned bc   = i0 >> 15;
    const long long a0  = ((long long)bc << 16) + ((long long)orow << 8) + pair;

    // four independent streaming loads (rows r, r+2, r+4, r+6)
    float4 v0 = __ldcs(&x[a0]);
    float4 v1 = __ldcs(&x[a0 +  512]);
    float4 v2 = __ldcs(&x[a0 + 1024]);
    float4 v3 = __ldcs(&x[a0 + 1536]);

    float2 o0, o1, o2, o3;
    o0.x = v0.x * 0.5f;  o0.y = v0.z * 0.5f;
    o1.x = v1.x * 0.5f;  o1.y = v1.z * 0.5f;
    o2.x = v2.x * 0.5f;  o2.y = v2.z * 0.5f;
    o3.x = v3.x * 0.5f;  o3.y = v3.z * 0.5f;

    // default write-back stores: L2 batches the write stream to DRAM
    out[i0]        = o0;
    out[i0 + 256u] = o1;
    out[i0 + 512u] = o2;
    out[i0 + 768u] = o3;
}

extern "C" void kernel_launch(void* const* d_in, const int* in_sizes, int n_in,
                              void* d_out, int out_size)
{
    const float4* x = (const float4*)d_in[0];
    float2* out     = (float2*)d_out;

    // out_size = 67,108,864 floats -> 33,554,432 pairs -> 1024 pairs per block
    long long n_pairs = (long long)out_size / 2;
    long long blocks  = n_pairs / 1024;                // 32768

    haar_sum_kernel<<<(unsigned)blocks, 256>>>(x, out);
}

// round 12
// speedup vs baseline: 1.0122x; 1.0119x over previous
#include <cuda_runtime.h>
#include <cstdint>

// out[b,c,h,w] = x[b,c,2h,2w] * 0.5f     (Haar DWT subband sum collapses to this)
// x:  [16, 64, 512, 512] fp32,  out: [16, 64, 256, 256] fp32
//
// FINAL (R8 configuration — best of 8 measured variants):
//   - flat grid (beats persistent loop: fresh CTAs keep the chip-wide
//     outstanding-load pool deep; grid-stride serializes behind store tails)
//   - MLP=4 front-batched loads (saturating; 2->4 gained, 4->8 neutral)
//   - __ldcs loads + __stcs stores (default write-back stores measured -2%)
//   - single index decomposition per thread (alu 9.5% -> 3.5%)
//   - fully warp-coalesced: every LDG.128 spans 512 contiguous bytes/warp,
//     every STG.64 spans 256 contiguous bytes/warp
//
// Geometry:
//   pair index p in [0, 33'554'432):  out float2 index = p
//   pair = p & 127, orow = (p>>7) & 255, bc = p >> 15
//   input float4 index = bc*65536 + orow*256 + pair   (even input row 2*orow)
//   block owns 1024 aligned pairs (8 output rows of one image), so
//   in_idx_k = in_idx_0 + 512k  (rows r, r+2, r+4, r+6), immediate offsets.
//
// Measured: 6.96 TB/s HBM (87.8% of spec), DRAM-bound at the mixed 2:1
// read/write + skip-alternate-2KB-row controller ceiling.

__global__ __launch_bounds__(256) void haar_sum_kernel(
    const float4* __restrict__ x, float2* __restrict__ out)
{
    const unsigned i0 = blockIdx.x * 1024u + threadIdx.x;

    // single index decomposition
    const unsigned pair = i0 & 127u;
    const unsigned orow = (i0 >> 7) & 255u;
    const unsigned bc   = i0 >> 15;
    const long long a0  = ((long long)bc << 16) + ((long long)orow << 8) + pair;

    // four independent streaming loads (rows r, r+2, r+4, r+6)
    float4 v0 = __ldcs(&x[a0]);
    float4 v1 = __ldcs(&x[a0 +  512]);
    float4 v2 = __ldcs(&x[a0 + 1024]);
    float4 v3 = __ldcs(&x[a0 + 1536]);

    float2 o0, o1, o2, o3;
    o0.x = v0.x * 0.5f;  o0.y = v0.z * 0.5f;
    o1.x = v1.x * 0.5f;  o1.y = v1.z * 0.5f;
    o2.x = v2.x * 0.5f;  o2.y = v2.z * 0.5f;
    o3.x = v3.x * 0.5f;  o3.y = v3.z * 0.5f;

    // streaming stores: avoid dirty-line write-back interference in L2
    __stcs(&out[i0],        o0);
    __stcs(&out[i0 + 256u], o1);
    __stcs(&out[i0 + 512u], o2);
    __stcs(&out[i0 + 768u], o3);
}

extern "C" void kernel_launch(void* const* d_in, const int* in_sizes, int n_in,
                              void* d_out, int out_size)
{
    const float4* x = (const float4*)d_in[0];
    float2* out     = (float2*)d_out;

    // out_size = 67,108,864 floats -> 33,554,432 pairs -> 1024 pairs per block
    long long n_pairs = (long long)out_size / 2;
    long long blocks  = n_pairs / 1024;                // 32768

    haar_sum_kernel<<<(unsigned)blocks, 256>>>(x, out);
}

// round 13
// speedup vs baseline: 1.0150x; 1.0027x over previous
#include <cuda_runtime.h>
#include <cstdint>

// out[b,c,h,w] = x[b,c,2h,2w] * 0.5f     (Haar DWT subband sum collapses to this)
// x:  [16, 64, 512, 512] fp32,  out: [16, 64, 256, 256] fp32
//
// R12 = R4 geometry (MLP=2, best measured wallclock) + R8 indexing
// (single decomposition per thread, best measured DRAM%):
//   - flat grid, 65536 blocks x 256 threads, each block owns 512 aligned pairs
//   - thread t handles pairs base+t and base+t+256
//   - +256 pairs = +2 output rows = +4 input rows = +512 float4, so the
//     second input address is a0 + 512 (immediate offset, no re-decompose)
//   - __ldcs loads, __stcs stores (both proven optimal in isolation)
//   - fully warp-coalesced: LDG.128 spans 512B/warp, STG.64 spans 256B/warp
//
// Geometry:
//   pair index p in [0, 33'554'432):  out float2 index = p
//   pair = p & 127, orow = (p>>7) & 255, bc = p >> 15
//   input float4 index = bc*65536 + orow*256 + pair   (even input row 2*orow)

__global__ __launch_bounds__(256) void haar_sum_kernel(
    const float4* __restrict__ x, float2* __restrict__ out)
{
    const unsigned i0 = blockIdx.x * 512u + threadIdx.x;

    // single index decomposition (bc/orow cannot wrap within an aligned 512-pair block)
    const unsigned pair = i0 & 127u;
    const unsigned orow = (i0 >> 7) & 255u;
    const unsigned bc   = i0 >> 15;
    const long long a0  = ((long long)bc << 16) + ((long long)orow << 8) + pair;

    // two independent streaming loads (input rows r and r+4)
    float4 v0 = __ldcs(&x[a0]);
    float4 v1 = __ldcs(&x[a0 + 512]);

    float2 o0, o1;
    o0.x = v0.x * 0.5f;  o0.y = v0.z * 0.5f;
    o1.x = v1.x * 0.5f;  o1.y = v1.z * 0.5f;

    __stcs(&out[i0],        o0);
    __stcs(&out[i0 + 256u], o1);
}

extern "C" void kernel_launch(void* const* d_in, const int* in_sizes, int n_in,
                              void* d_out, int out_size)
{
    const float4* x = (const float4*)d_in[0];
    float2* out     = (float2*)d_out;

    // out_size = 67,108,864 floats -> 33,554,432 pairs -> 512 pairs per block
    long long n_pairs = (long long)out_size / 2;
    long long blocks  = n_pairs / 512;                 // 65536

    haar_sum_kernel<<<(unsigned)blocks, 256>>>(x, out);
}